// round 3
// baseline (speedup 1.0000x reference)
#include <cuda_runtime.h>
#include <cstdint>

// SlidingKVQCache on GB300: out = concat over {k,v,q} of (cache shifted left 1
// token, new token appended). Caches [4,32,2048,128] fp32, tokens [4,32,1,128].
//
// Flat per-cache view (float4 units): slab = 2048*32 = 65536 = 2^16 per (b,h).
//   out[i] = cache[i + 32]                         if (i & 65535) < 65504
//   out[i] = tok[(i>>16)*32 + ((i&65535)-65504)]   otherwise (last token row)
//
// Single-wave persistent kernel: grid (256, 3) = 768 blocks (all resident),
// each block runs exactly 16 iterations of 2048 float4, U=8 front-batched
// streaming loads/stores (128 B/thread/iter).

static constexpr unsigned SLABMASK = 65535u;
static constexpr unsigned TAIL4    = 65504u;
static constexpr unsigned CACHE4   = 1u << 23;          // 8388608 float4 per cache

static constexpr int THREADS = 256;
static constexpr int U = 8;
static constexpr unsigned PER_ITER  = THREADS * U;      // 2048 float4 per block-iter
static constexpr unsigned GRID_X    = 256;
static constexpr unsigned NUM_ITERS = CACHE4 / (PER_ITER * GRID_X);  // 16, exact

__global__ __launch_bounds__(THREADS, 8)
void sliding_cache_persist_kernel(
    const float4* __restrict__ kc,
    const float4* __restrict__ vc,
    const float4* __restrict__ qc,
    const float4* __restrict__ kt,
    const float4* __restrict__ vt,
    const float4* __restrict__ qt,
    float4* __restrict__ out)
{
    const int c = blockIdx.y;
    const float4* __restrict__ cache = (c == 0) ? kc : (c == 1) ? vc : qc;
    const float4* __restrict__ tok   = (c == 0) ? kt : (c == 1) ? vt : qt;
    float4* __restrict__ ob = out + (size_t)c * CACHE4;

    unsigned base = blockIdx.x * PER_ITER + threadIdx.x;

    for (unsigned t = 0; t < NUM_ITERS; t++) {
        unsigned idx[U];
        const float4* __restrict__ src[U];

        #pragma unroll
        for (int k = 0; k < U; k++) {
            idx[k] = base + (unsigned)k * THREADS;
            unsigned pos = idx[k] & SLABMASK;
            src[k] = (pos < TAIL4)
                   ? cache + idx[k] + 32
                   : tok + ((idx[k] >> 16) << 5) + (pos - TAIL4);
        }

        float4 v[U];
        #pragma unroll
        for (int k = 0; k < U; k++) v[k] = __ldcs(src[k]);   // front-batched, evict-first

        #pragma unroll
        for (int k = 0; k < U; k++) __stcs(ob + idx[k], v[k]);

        base += GRID_X * PER_ITER;   // 524288
    }
}

extern "C" void kernel_launch(void* const* d_in, const int* in_sizes, int n_in,
                              void* d_out, int out_size)
{
    const float4* kc = (const float4*)d_in[0];
    const float4* vc = (const float4*)d_in[1];
    const float4* qc = (const float4*)d_in[2];
    const float4* kt = (const float4*)d_in[3];
    const float4* vt = (const float4*)d_in[4];
    const float4* qt = (const float4*)d_in[5];
    float4* out = (float4*)d_out;

    dim3 grid(GRID_X, 3, 1);   // 768 blocks — single wave on 148+ SMs at 8 blocks/SM
    sliding_cache_persist_kernel<<<grid, THREADS>>>(kc, vc, qc, kt, vt, qt, out);
}

// round 4
// speedup vs baseline: 1.2108x; 1.2108x over previous
#include <cuda_runtime.h>
#include <cstdint>

// SlidingKVQCache on GB300: out = concat over {k,v,q} of (cache shifted left 1
// token, new token appended). Caches [4,32,2048,128] fp32, tokens [4,32,1,128].
//
// Flat per-cache view (float4 units): slab = 2048*32 = 65536 = 2^16 per (b,h).
//   out[i] = cache[i + 32]                         if (i & 65535) < 65504
//   out[i] = tok[(i>>16)*32 + ((i&65535)-65504)]   otherwise (last token row)
//
// R4: R2 structure (large grid, full occupancy) + U=8 front-batched streaming
// loads (128 B/thread). One block handles 2048 consecutive float4.

static constexpr unsigned SLABMASK = 65535u;
static constexpr unsigned TAIL4    = 65504u;
static constexpr unsigned CACHE4   = 1u << 23;          // 8388608 float4 per cache

static constexpr int THREADS = 256;
static constexpr int U = 8;                             // float4 per thread
static constexpr unsigned PER_BLOCK = THREADS * U;      // 2048

__global__ __launch_bounds__(THREADS, 8)
void sliding_cache_flat8_kernel(
    const float4* __restrict__ kc,
    const float4* __restrict__ vc,
    const float4* __restrict__ qc,
    const float4* __restrict__ kt,
    const float4* __restrict__ vt,
    const float4* __restrict__ qt,
    float4* __restrict__ out)
{
    const int c = blockIdx.y;
    const float4* __restrict__ cache = (c == 0) ? kc : (c == 1) ? vc : qc;
    const float4* __restrict__ tok   = (c == 0) ? kt : (c == 1) ? vt : qt;
    float4* __restrict__ ob = out + (size_t)c * CACHE4;

    const unsigned base = blockIdx.x * PER_BLOCK + threadIdx.x;

    unsigned idx[U];
    const float4* __restrict__ src[U];

    #pragma unroll
    for (int k = 0; k < U; k++) {
        idx[k] = base + (unsigned)k * THREADS;
        unsigned pos = idx[k] & SLABMASK;
        src[k] = (pos < TAIL4)
               ? cache + idx[k] + 32
               : tok + ((idx[k] >> 16) << 5) + (pos - TAIL4);
    }

    float4 v[U];
    #pragma unroll
    for (int k = 0; k < U; k++) v[k] = __ldcs(src[k]);   // front-batched x8, evict-first

    #pragma unroll
    for (int k = 0; k < U; k++) __stcs(ob + idx[k], v[k]);
}

extern "C" void kernel_launch(void* const* d_in, const int* in_sizes, int n_in,
                              void* d_out, int out_size)
{
    const float4* kc = (const float4*)d_in[0];
    const float4* vc = (const float4*)d_in[1];
    const float4* qc = (const float4*)d_in[2];
    const float4* kt = (const float4*)d_in[3];
    const float4* vt = (const float4*)d_in[4];
    const float4* qt = (const float4*)d_in[5];
    float4* out = (float4*)d_out;

    dim3 grid(CACHE4 / PER_BLOCK, 3, 1);   // 4096 x 3 = 12288 blocks
    sliding_cache_flat8_kernel<<<grid, THREADS>>>(kc, vc, qc, kt, vt, qt, out);
}

// round 5
// speedup vs baseline: 1.2528x; 1.0347x over previous
#include <cuda_runtime.h>
#include <cstdint>

// SlidingKVQCache on GB300: out = concat over {k,v,q} of (cache shifted left 1
// token, new token appended). Caches [4,32,2048,128] fp32, tokens [4,32,1,128].
//
// Flat per-cache view (float4 units): slab = 2048*32 = 65536 = 2^16 per (b,h).
//   out[i] = cache[i + 32]                         if (i & 65535) < 65504
//   out[i] = tok[(i>>16)*32 + ((i&65535)-65504)]   otherwise (last token row)
//
// R5: R2 winner config (U=4, 256 threads, 24576 blocks) + __ldcs evict-first
// reads (single-touch stream), plain stores.

static constexpr unsigned SLABMASK = 65535u;
static constexpr unsigned TAIL4    = 65504u;
static constexpr unsigned CACHE4   = 1u << 23;          // 8388608 float4 per cache

static constexpr int THREADS = 256;
static constexpr int U = 4;                             // float4 per thread
static constexpr unsigned PER_BLOCK = THREADS * U;      // 1024

__global__ __launch_bounds__(THREADS, 8)
void sliding_cache_flat4s_kernel(
    const float4* __restrict__ kc,
    const float4* __restrict__ vc,
    const float4* __restrict__ qc,
    const float4* __restrict__ kt,
    const float4* __restrict__ vt,
    const float4* __restrict__ qt,
    float4* __restrict__ out)
{
    const int c = blockIdx.y;
    const float4* __restrict__ cache = (c == 0) ? kc : (c == 1) ? vc : qc;
    const float4* __restrict__ tok   = (c == 0) ? kt : (c == 1) ? vt : qt;
    float4* __restrict__ ob = out + (size_t)c * CACHE4;

    const unsigned base = blockIdx.x * PER_BLOCK + threadIdx.x;

    unsigned idx[U];
    const float4* __restrict__ src[U];

    #pragma unroll
    for (int k = 0; k < U; k++) {
        idx[k] = base + (unsigned)k * THREADS;
        unsigned pos = idx[k] & SLABMASK;
        src[k] = (pos < TAIL4)
               ? cache + idx[k] + 32
               : tok + ((idx[k] >> 16) << 5) + (pos - TAIL4);
    }

    float4 v[U];
    #pragma unroll
    for (int k = 0; k < U; k++) v[k] = __ldcs(src[k]);   // front-batched x4, evict-first

    #pragma unroll
    for (int k = 0; k < U; k++) ob[idx[k]] = v[k];       // plain STG.128

    // (no tail handling needed: CACHE4 is an exact multiple of PER_BLOCK)
}

extern "C" void kernel_launch(void* const* d_in, const int* in_sizes, int n_in,
                              void* d_out, int out_size)
{
    const float4* kc = (const float4*)d_in[0];
    const float4* vc = (const float4*)d_in[1];
    const float4* qc = (const float4*)d_in[2];
    const float4* kt = (const float4*)d_in[3];
    const float4* vt = (const float4*)d_in[4];
    const float4* qt = (const float4*)d_in[5];
    float4* out = (float4*)d_out;

    dim3 grid(CACHE4 / PER_BLOCK, 3, 1);   // 8192 x 3 = 24576 blocks
    sliding_cache_flat4s_kernel<<<grid, THREADS>>>(kc, vc, qc, kt, vt, qt, out);
}